// round 6
// baseline (speedup 1.0000x reference)
#include <cuda_runtime.h>
#include <cstdint>

#define N_NODES 50000
#define E_EDGES 600000
#define FDIM 128
#define OUTD 12

// ---------------- scratch (device globals; no runtime allocation) ------------
__device__ float g_deg[N_NODES];
__device__ float g_dinv[N_NODES];
__device__ float g_agg[(size_t)N_NODES * FDIM];          // A_norm @ x
__device__ float g_gate[(size_t)3 * N_NODES * FDIM];     // gz, gr, gh
__device__ float g_Z[(size_t)N_NODES * FDIM];
__device__ float g_R[(size_t)N_NODES * FDIM];

// ---------------- degree / norm ----------------------------------------------
__global__ void k_init_deg() {
    int i = blockIdx.x * blockDim.x + threadIdx.x;
    if (i < N_NODES) g_deg[i] = 1.0f;   // self-loop weight
}

__global__ void k_deg_acc(const int* __restrict__ ei,
                          const float* __restrict__ ew) {
    for (int e = blockIdx.x * blockDim.x + threadIdx.x; e < E_EDGES;
         e += gridDim.x * blockDim.x) {
        int d = ei[E_EDGES + e];
        atomicAdd(&g_deg[d], ew[e]);
    }
}

// dinv = rsqrt(deg); agg[i] = x[i] * dinv[i]^2  (self-loop contribution)
// one warp per node
__global__ void k_dinv_self(const float* __restrict__ x) {
    int warp = (blockIdx.x * blockDim.x + threadIdx.x) >> 5;
    int lane = threadIdx.x & 31;
    if (warp >= N_NODES) return;
    float s;
    if (lane == 0) {
        float dg = g_deg[warp];
        s = (dg > 0.0f) ? rsqrtf(dg) : 0.0f;
        g_dinv[warp] = s;
    }
    s = __shfl_sync(0xffffffffu, s, 0);
    float s2 = s * s;
    size_t off = (size_t)warp * FDIM + lane * 4;
    float4 v = *(const float4*)(x + off);
    v.x *= s2; v.y *= s2; v.z *= s2; v.w *= s2;
    *(float4*)(g_agg + off) = v;
}

// one warp per edge: agg[dst] += x[src] * (dinv[src]*w*dinv[dst])
__global__ void k_edge_agg(const int* __restrict__ ei,
                           const float* __restrict__ ew,
                           const float* __restrict__ x) {
    int warp = (blockIdx.x * blockDim.x + threadIdx.x) >> 5;
    int lane = threadIdx.x & 31;
    if (warp >= E_EDGES) return;
    int s = 0, d = 0;
    float norm = 0.0f;
    if (lane == 0) {
        s = ei[warp];
        d = ei[E_EDGES + warp];
        norm = g_dinv[s] * ew[warp] * g_dinv[d];
    }
    s = __shfl_sync(0xffffffffu, s, 0);
    d = __shfl_sync(0xffffffffu, d, 0);
    norm = __shfl_sync(0xffffffffu, norm, 0);
    float4 v = *(const float4*)(x + (size_t)s * FDIM + lane * 4);
    float* p = g_agg + (size_t)d * FDIM + lane * 4;
    atomicAdd(p + 0, v.x * norm);
    atomicAdd(p + 1, v.y * norm);
    atomicAdd(p + 2, v.z * norm);
    atomicAdd(p + 3, v.w * norm);
}

// ---------------- GEMM 1: gz/gr/gh = agg @ W + b  (blockIdx.y = gate) --------
__global__ void __launch_bounds__(256)
k_gates_gemm(const float* __restrict__ Wz, const float* __restrict__ bz,
             const float* __restrict__ Wr, const float* __restrict__ br,
             const float* __restrict__ Wh, const float* __restrict__ bh) {
    int gate = blockIdx.y;
    const float* W = (gate == 0) ? Wz : (gate == 1) ? Wr : Wh;
    const float* b = (gate == 0) ? bz : (gate == 1) ? br : bh;
    float* C = g_gate + (size_t)gate * N_NODES * FDIM;
    const float* A = g_agg;

    __shared__ float As[64][16];
    __shared__ float Ws[16][128];

    int tid = threadIdx.x;
    int tx = tid & 31, ty = tid >> 5;
    int row0 = blockIdx.x * 64;

    float acc[8][4] = {};

    for (int kk = 0; kk < 128; kk += 16) {
        {   // A tile: 64x16
            int r = tid >> 2, c4 = tid & 3;
            int row = row0 + r;
            float4 v = make_float4(0.f, 0.f, 0.f, 0.f);
            if (row < N_NODES)
                v = *(const float4*)(A + (size_t)row * FDIM + kk + c4 * 4);
            *(float4*)&As[r][c4 * 4] = v;
        }
        {   // W tile: 16x128
            #pragma unroll
            for (int t = 0; t < 2; t++) {
                int idx = tid + t * 256;
                int r = idx >> 5, c = (idx & 31) * 4;
                *(float4*)&Ws[r][c] = *(const float4*)(W + (size_t)(kk + r) * FDIM + c);
            }
        }
        __syncthreads();
        #pragma unroll
        for (int k = 0; k < 16; k++) {
            float4 wv = *(float4*)&Ws[k][tx * 4];
            #pragma unroll
            for (int i = 0; i < 8; i++) {
                float a = As[ty * 8 + i][k];
                acc[i][0] += a * wv.x; acc[i][1] += a * wv.y;
                acc[i][2] += a * wv.z; acc[i][3] += a * wv.w;
            }
        }
        __syncthreads();
    }
    float4 bv = *(const float4*)(b + tx * 4);
    #pragma unroll
    for (int i = 0; i < 8; i++) {
        int row = row0 + ty * 8 + i;
        if (row < N_NODES) {
            float4 o = make_float4(acc[i][0] + bv.x, acc[i][1] + bv.y,
                                   acc[i][2] + bv.z, acc[i][3] + bv.w);
            *(float4*)(C + (size_t)row * FDIM + tx * 4) = o;
        }
    }
}

// ---------------- GEMM 2: Z = sig([gz,H]@Lz+lbz), R = sig([gr,H]@Lr+lbr) -----
__global__ void __launch_bounds__(256)
k_zr_gemm(const float* __restrict__ H,
          const float* __restrict__ Lz, const float* __restrict__ lbz,
          const float* __restrict__ Lr, const float* __restrict__ lbr) {
    int which = blockIdx.y;  // 0=Z, 1=R
    const float* G = g_gate + (size_t)which * N_NODES * FDIM;
    const float* L = (which == 0) ? Lz : Lr;
    const float* lb = (which == 0) ? lbz : lbr;
    float* C = (which == 0) ? g_Z : g_R;

    __shared__ float As[64][16];
    __shared__ float Ws[16][128];

    int tid = threadIdx.x;
    int tx = tid & 31, ty = tid >> 5;
    int row0 = blockIdx.x * 64;

    float acc[8][4] = {};

    for (int kk = 0; kk < 256; kk += 16) {
        {
            int r = tid >> 2, c4 = tid & 3;
            int row = row0 + r;
            const float* Asrc = (kk < 128) ? G : H;
            int col = (kk < 128) ? (kk + c4 * 4) : (kk - 128 + c4 * 4);
            float4 v = make_float4(0.f, 0.f, 0.f, 0.f);
            if (row < N_NODES)
                v = *(const float4*)(Asrc + (size_t)row * FDIM + col);
            *(float4*)&As[r][c4 * 4] = v;
        }
        {
            #pragma unroll
            for (int t = 0; t < 2; t++) {
                int idx = tid + t * 256;
                int r = idx >> 5, c = (idx & 31) * 4;
                *(float4*)&Ws[r][c] = *(const float4*)(L + (size_t)(kk + r) * FDIM + c);
            }
        }
        __syncthreads();
        #pragma unroll
        for (int k = 0; k < 16; k++) {
            float4 wv = *(float4*)&Ws[k][tx * 4];
            #pragma unroll
            for (int i = 0; i < 8; i++) {
                float a = As[ty * 8 + i][k];
                acc[i][0] += a * wv.x; acc[i][1] += a * wv.y;
                acc[i][2] += a * wv.z; acc[i][3] += a * wv.w;
            }
        }
        __syncthreads();
    }
    float4 bv = *(const float4*)(lb + tx * 4);
    #pragma unroll
    for (int i = 0; i < 8; i++) {
        int row = row0 + ty * 8 + i;
        if (row < N_NODES) {
            float4 o;
            o.x = 1.0f / (1.0f + expf(-(acc[i][0] + bv.x)));
            o.y = 1.0f / (1.0f + expf(-(acc[i][1] + bv.y)));
            o.z = 1.0f / (1.0f + expf(-(acc[i][2] + bv.z)));
            o.w = 1.0f / (1.0f + expf(-(acc[i][3] + bv.w)));
            *(float4*)(C + (size_t)row * FDIM + tx * 4) = o;
        }
    }
}

// ------ GEMM 3 (fused): Ht = tanh([gh, H*R]@Lh+lbh); h = Z*H+(1-Z)*Ht;
//                        y = relu(h)@Wo + bo ---------------------------------
__global__ void __launch_bounds__(256)
k_final(const float* __restrict__ H,
        const float* __restrict__ Lh, const float* __restrict__ lbh,
        const float* __restrict__ Wo, const float* __restrict__ bo,
        float* __restrict__ y_out, float* __restrict__ h_out) {
    extern __shared__ float sm[];
    float* As = sm;                 // 64*16
    float* Ws = sm + 64 * 16;       // 16*128
    // epilogue reuse:
    float* hs = sm;                 // 64*132 (relu(h))
    float* Wos = sm + 64 * 132;     // 128*12

    const float* Gh = g_gate + (size_t)2 * N_NODES * FDIM;

    int tid = threadIdx.x;
    int tx = tid & 31, ty = tid >> 5;
    int row0 = blockIdx.x * 64;

    float acc[8][4] = {};

    for (int kk = 0; kk < 256; kk += 16) {
        {
            int r = tid >> 2, c4 = tid & 3;
            int row = row0 + r;
            float4 v = make_float4(0.f, 0.f, 0.f, 0.f);
            if (row < N_NODES) {
                if (kk < 128) {
                    v = *(const float4*)(Gh + (size_t)row * FDIM + kk + c4 * 4);
                } else {
                    int col = kk - 128 + c4 * 4;
                    float4 hv = *(const float4*)(H + (size_t)row * FDIM + col);
                    float4 rv = *(const float4*)(g_R + (size_t)row * FDIM + col);
                    v.x = hv.x * rv.x; v.y = hv.y * rv.y;
                    v.z = hv.z * rv.z; v.w = hv.w * rv.w;
                }
            }
            *(float4*)&As[r * 16 + c4 * 4] = v;
        }
        {
            #pragma unroll
            for (int t = 0; t < 2; t++) {
                int idx = tid + t * 256;
                int r = idx >> 5, c = (idx & 31) * 4;
                *(float4*)&Ws[r * 128 + c] = *(const float4*)(Lh + (size_t)(kk + r) * FDIM + c);
            }
        }
        __syncthreads();
        #pragma unroll
        for (int k = 0; k < 16; k++) {
            float4 wv = *(float4*)&Ws[k * 128 + tx * 4];
            #pragma unroll
            for (int i = 0; i < 8; i++) {
                float a = As[(ty * 8 + i) * 16 + k];
                acc[i][0] += a * wv.x; acc[i][1] += a * wv.y;
                acc[i][2] += a * wv.z; acc[i][3] += a * wv.w;
            }
        }
        __syncthreads();
    }

    // epilogue: h, relu(h) -> hs
    float4 bv = *(const float4*)(lbh + tx * 4);
    #pragma unroll
    for (int i = 0; i < 8; i++) {
        int lr = ty * 8 + i;
        int row = row0 + lr;
        float4 hres = make_float4(0.f, 0.f, 0.f, 0.f);
        if (row < N_NODES) {
            float4 Zv = *(const float4*)(g_Z + (size_t)row * FDIM + tx * 4);
            float4 Hv = *(const float4*)(H + (size_t)row * FDIM + tx * 4);
            float t0 = tanhf(acc[i][0] + bv.x);
            float t1 = tanhf(acc[i][1] + bv.y);
            float t2 = tanhf(acc[i][2] + bv.z);
            float t3 = tanhf(acc[i][3] + bv.w);
            hres.x = Zv.x * Hv.x + (1.0f - Zv.x) * t0;
            hres.y = Zv.y * Hv.y + (1.0f - Zv.y) * t1;
            hres.z = Zv.z * Hv.z + (1.0f - Zv.z) * t2;
            hres.w = Zv.w * Hv.w + (1.0f - Zv.w) * t3;
            *(float4*)(h_out + (size_t)row * FDIM + tx * 4) = hres;
        }
        hs[lr * 132 + tx * 4 + 0] = fmaxf(hres.x, 0.0f);
        hs[lr * 132 + tx * 4 + 1] = fmaxf(hres.y, 0.0f);
        hs[lr * 132 + tx * 4 + 2] = fmaxf(hres.z, 0.0f);
        hs[lr * 132 + tx * 4 + 3] = fmaxf(hres.w, 0.0f);
    }
    // load Wo
    for (int t = tid; t < FDIM * OUTD; t += 256) Wos[t] = Wo[t];
    __syncthreads();

    // y = relu(h) @ Wo + bo : each thread -> 1 row x 3 out-cols
    {
        int r = tid >> 2;
        int og = (tid & 3) * 3;
        float a0 = 0.f, a1 = 0.f, a2 = 0.f;
        #pragma unroll 8
        for (int k = 0; k < FDIM; k++) {
            float hv = hs[r * 132 + k];
            a0 += hv * Wos[k * OUTD + og + 0];
            a1 += hv * Wos[k * OUTD + og + 1];
            a2 += hv * Wos[k * OUTD + og + 2];
        }
        int row = row0 + r;
        if (row < N_NODES) {
            y_out[(size_t)row * OUTD + og + 0] = a0 + bo[og + 0];
            y_out[(size_t)row * OUTD + og + 1] = a1 + bo[og + 1];
            y_out[(size_t)row * OUTD + og + 2] = a2 + bo[og + 2];
        }
    }
}

// ---------------- launch ------------------------------------------------------
extern "C" void kernel_launch(void* const* d_in, const int* in_sizes, int n_in,
                              void* d_out, int out_size) {
    const float* x  = (const float*)d_in[0];
    const int*   ei = (const int*)d_in[1];      // edge_index as int32 (harness dtype)
    const float* ew = (const float*)d_in[2];
    const float* H  = (const float*)d_in[3];
    const float* Wz = (const float*)d_in[4];
    const float* bz = (const float*)d_in[5];
    const float* Wr = (const float*)d_in[6];
    const float* br = (const float*)d_in[7];
    const float* Wh = (const float*)d_in[8];
    const float* bh = (const float*)d_in[9];
    const float* Lz = (const float*)d_in[10];
    const float* lbz = (const float*)d_in[11];
    const float* Lr = (const float*)d_in[12];
    const float* lbr = (const float*)d_in[13];
    const float* Lh = (const float*)d_in[14];
    const float* lbh = (const float*)d_in[15];
    const float* Wo = (const float*)d_in[16];
    const float* bo = (const float*)d_in[17];

    float* y_out = (float*)d_out;                           // (N, 12)
    float* h_out = (float*)d_out + (size_t)N_NODES * OUTD;  // (N, 128)

    int nblk = (N_NODES + 63) / 64;   // 782

    k_init_deg<<<(N_NODES + 255) / 256, 256>>>();
    k_deg_acc<<<592, 256>>>(ei, ew);
    k_dinv_self<<<(N_NODES * 32 + 255) / 256, 256>>>(x);
    k_edge_agg<<<(E_EDGES * 32 + 255) / 256, 256>>>(ei, ew, x);
    k_gates_gemm<<<dim3(nblk, 3), 256>>>(Wz, bz, Wr, br, Wh, bh);
    k_zr_gemm<<<dim3(nblk, 2), 256>>>(H, Lz, lbz, Lr, lbr);
    k_final<<<nblk, 256, (64 * 132 + 128 * 12) * sizeof(float)>>>(
        H, Lh, lbh, Wo, bo, y_out, h_out);
}

// round 9
// speedup vs baseline: 1.1147x; 1.1147x over previous
#include <cuda_runtime.h>
#include <cstdint>

#define N_NODES 50000
#define E_EDGES 600000
#define FDIM 128
#define OUTD 12

// ---------------- scratch (device globals; no runtime allocation) ------------
__device__ float g_deg[N_NODES];
__device__ float g_dinv[N_NODES];
__device__ float g_agg[(size_t)N_NODES * FDIM];          // A_norm @ x
__device__ float g_gate[(size_t)3 * N_NODES * FDIM];     // gz, gr, gh (gz slot reused as relu(h))
__device__ float g_Z[(size_t)N_NODES * FDIM];
__device__ float g_R[(size_t)N_NODES * FDIM];

// ---------------- degree / norm ----------------------------------------------
__global__ void k_init_deg() {
    int i = blockIdx.x * blockDim.x + threadIdx.x;
    if (i < N_NODES) g_deg[i] = 1.0f;   // self-loop weight
}

__global__ void k_deg_acc(const int* __restrict__ ei,
                          const float* __restrict__ ew) {
    for (int e = blockIdx.x * blockDim.x + threadIdx.x; e < E_EDGES;
         e += gridDim.x * blockDim.x) {
        int d = ei[E_EDGES + e];
        atomicAdd(&g_deg[d], ew[e]);
    }
}

// dinv = rsqrt(deg); agg[i] = x[i] * dinv[i]^2  (self-loop), one warp per node
__global__ void k_dinv_self(const float* __restrict__ x) {
    int warp = (blockIdx.x * blockDim.x + threadIdx.x) >> 5;
    int lane = threadIdx.x & 31;
    if (warp >= N_NODES) return;
    float s;
    if (lane == 0) {
        float dg = g_deg[warp];
        s = (dg > 0.0f) ? rsqrtf(dg) : 0.0f;
        g_dinv[warp] = s;
    }
    s = __shfl_sync(0xffffffffu, s, 0);
    float s2 = s * s;
    size_t off = (size_t)warp * FDIM + lane * 4;
    float4 v = *(const float4*)(x + off);
    v.x *= s2; v.y *= s2; v.z *= s2; v.w *= s2;
    *(float4*)(g_agg + off) = v;
}

// one warp per edge: agg[dst] += x[src] * (dinv[src]*w*dinv[dst]); vectorized red
__global__ void k_edge_agg(const int* __restrict__ ei,
                           const float* __restrict__ ew,
                           const float* __restrict__ x) {
    int warp = (blockIdx.x * blockDim.x + threadIdx.x) >> 5;
    int lane = threadIdx.x & 31;
    if (warp >= E_EDGES) return;
    int s = 0, d = 0;
    float norm = 0.0f;
    if (lane == 0) {
        s = ei[warp];
        d = ei[E_EDGES + warp];
        norm = g_dinv[s] * ew[warp] * g_dinv[d];
    }
    s = __shfl_sync(0xffffffffu, s, 0);
    d = __shfl_sync(0xffffffffu, d, 0);
    norm = __shfl_sync(0xffffffffu, norm, 0);
    float4 v = *(const float4*)(x + (size_t)s * FDIM + lane * 4);
    float* p = g_agg + (size_t)d * FDIM + lane * 4;
    asm volatile("red.global.add.v4.f32 [%0], {%1,%2,%3,%4};"
                 :: "l"(p), "f"(v.x * norm), "f"(v.y * norm),
                    "f"(v.z * norm), "f"(v.w * norm)
                 : "memory");
}

// ======================= 128x128 fp32 GEMM tiles ==============================
// 256 threads, thread (tx,ty) = (tid&15, tid>>4) owns 8x8 micro-tile.
// As stored k-major (transposed) so compute phase is LDS.128 only.

#define GEMM_SMEM  __shared__ float As[16][136]; __shared__ float Ws[16][136];

#define GEMM_LOAD_W(Wsrc, kk)                                              \
    _Pragma("unroll")                                                      \
    for (int t = 0; t < 2; t++) {                                          \
        int idx = tid + t * 256;                                           \
        int r = idx >> 5, c = (idx & 31) * 4;                              \
        *(float4*)&Ws[r][c] = *(const float4*)((Wsrc) + (size_t)((kk) + r) * FDIM + c); \
    }

#define GEMM_STORE_A(v0, v1)                                               \
    As[kq + 0][lrow] = v0.x; As[kq + 1][lrow] = v0.y;                      \
    As[kq + 2][lrow] = v0.z; As[kq + 3][lrow] = v0.w;                      \
    As[kq + 4][lrow] = v1.x; As[kq + 5][lrow] = v1.y;                      \
    As[kq + 6][lrow] = v1.z; As[kq + 7][lrow] = v1.w;

#define GEMM_COMPUTE                                                       \
    _Pragma("unroll")                                                      \
    for (int k = 0; k < 16; k++) {                                         \
        float a[8], b[8];                                                  \
        *(float4*)&a[0] = *(float4*)&As[k][ty * 8];                        \
        *(float4*)&a[4] = *(float4*)&As[k][ty * 8 + 4];                    \
        *(float4*)&b[0] = *(float4*)&Ws[k][tx * 8];                        \
        *(float4*)&b[4] = *(float4*)&Ws[k][tx * 8 + 4];                    \
        _Pragma("unroll")                                                  \
        for (int i = 0; i < 8; i++)                                        \
            _Pragma("unroll")                                              \
            for (int j = 0; j < 8; j++)                                    \
                acc[i][j] += a[i] * b[j];                                  \
    }

// ---------------- GEMM 1: gz/gr/gh = agg @ W + b  (blockIdx.y = gate) --------
__global__ void __launch_bounds__(256, 2)
k_gates_gemm(const float* __restrict__ Wz, const float* __restrict__ bz,
             const float* __restrict__ Wr, const float* __restrict__ br,
             const float* __restrict__ Wh, const float* __restrict__ bh) {
    int gate = blockIdx.y;
    const float* W = (gate == 0) ? Wz : (gate == 1) ? Wr : Wh;
    const float* b = (gate == 0) ? bz : (gate == 1) ? br : bh;
    float* C = g_gate + (size_t)gate * N_NODES * FDIM;

    GEMM_SMEM
    int tid = threadIdx.x, tx = tid & 15, ty = tid >> 4;
    int row0 = blockIdx.x * 128;
    int lrow = tid >> 1, kq = (tid & 1) * 8;
    int grow = row0 + lrow;
    float acc[8][8] = {};

    for (int kk = 0; kk < 128; kk += 16) {
        float4 v0 = make_float4(0.f,0.f,0.f,0.f), v1 = v0;
        if (grow < N_NODES) {
            const float* src = g_agg + (size_t)grow * FDIM + kk + kq;
            v0 = *(const float4*)src; v1 = *(const float4*)(src + 4);
        }
        GEMM_STORE_A(v0, v1)
        GEMM_LOAD_W(W, kk)
        __syncthreads();
        GEMM_COMPUTE
        __syncthreads();
    }
    float4 b0 = *(const float4*)(b + tx * 8);
    float4 b1 = *(const float4*)(b + tx * 8 + 4);
    #pragma unroll
    for (int i = 0; i < 8; i++) {
        int row = row0 + ty * 8 + i;
        if (row < N_NODES) {
            float* dst = C + (size_t)row * FDIM + tx * 8;
            *(float4*)dst = make_float4(acc[i][0]+b0.x, acc[i][1]+b0.y,
                                        acc[i][2]+b0.z, acc[i][3]+b0.w);
            *(float4*)(dst+4) = make_float4(acc[i][4]+b1.x, acc[i][5]+b1.y,
                                            acc[i][6]+b1.z, acc[i][7]+b1.w);
        }
    }
}

// ---------------- GEMM 2: Z = sig([gz,H]@Lz+lbz), R = sig([gr,H]@Lr+lbr) -----
__global__ void __launch_bounds__(256, 2)
k_zr_gemm(const float* __restrict__ H,
          const float* __restrict__ Lz, const float* __restrict__ lbz,
          const float* __restrict__ Lr, const float* __restrict__ lbr) {
    int which = blockIdx.y;  // 0=Z, 1=R
    const float* G = g_gate + (size_t)which * N_NODES * FDIM;
    const float* L = (which == 0) ? Lz : Lr;
    const float* lb = (which == 0) ? lbz : lbr;
    float* C = (which == 0) ? g_Z : g_R;

    GEMM_SMEM
    int tid = threadIdx.x, tx = tid & 15, ty = tid >> 4;
    int row0 = blockIdx.x * 128;
    int lrow = tid >> 1, kq = (tid & 1) * 8;
    int grow = row0 + lrow;
    float acc[8][8] = {};

    for (int kk = 0; kk < 256; kk += 16) {
        float4 v0 = make_float4(0.f,0.f,0.f,0.f), v1 = v0;
        if (grow < N_NODES) {
            const float* Asrc = (kk < 128) ? G : H;
            int col = (kk < 128) ? (kk + kq) : (kk - 128 + kq);
            const float* src = Asrc + (size_t)grow * FDIM + col;
            v0 = *(const float4*)src; v1 = *(const float4*)(src + 4);
        }
        GEMM_STORE_A(v0, v1)
        GEMM_LOAD_W(L, kk)
        __syncthreads();
        GEMM_COMPUTE
        __syncthreads();
    }
    float4 b0 = *(const float4*)(lb + tx * 8);
    float4 b1 = *(const float4*)(lb + tx * 8 + 4);
    float bb[8] = {b0.x,b0.y,b0.z,b0.w,b1.x,b1.y,b1.z,b1.w};
    #pragma unroll
    for (int i = 0; i < 8; i++) {
        int row = row0 + ty * 8 + i;
        if (row < N_NODES) {
            float o[8];
            #pragma unroll
            for (int j = 0; j < 8; j++)
                o[j] = 1.0f / (1.0f + __expf(-(acc[i][j] + bb[j])));
            float* dst = C + (size_t)row * FDIM + tx * 8;
            *(float4*)dst = make_float4(o[0],o[1],o[2],o[3]);
            *(float4*)(dst+4) = make_float4(o[4],o[5],o[6],o[7]);
        }
    }
}

// ------ GEMM 3: Ht = tanh([gh, H*R]@Lh+lbh); h = Z*H+(1-Z)*Ht ----------------
// writes h_out and relu(h) -> g_gate[0] scratch (gz already consumed)
__global__ void __launch_bounds__(256, 2)
k_final(const float* __restrict__ H,
        const float* __restrict__ Lh, const float* __restrict__ lbh,
        float* __restrict__ h_out) {
    const float* Gh = g_gate + (size_t)2 * N_NODES * FDIM;
    float* relu_s = g_gate;   // scratch reuse

    GEMM_SMEM
    int tid = threadIdx.x, tx = tid & 15, ty = tid >> 4;
    int row0 = blockIdx.x * 128;
    int lrow = tid >> 1, kq = (tid & 1) * 8;
    int grow = row0 + lrow;
    float acc[8][8] = {};

    for (int kk = 0; kk < 256; kk += 16) {
        float4 v0 = make_float4(0.f,0.f,0.f,0.f), v1 = v0;
        if (grow < N_NODES) {
            if (kk < 128) {
                const float* src = Gh + (size_t)grow * FDIM + kk + kq;
                v0 = *(const float4*)src; v1 = *(const float4*)(src + 4);
            } else {
                int col = kk - 128 + kq;
                const float* hp = H + (size_t)grow * FDIM + col;
                const float* rp = g_R + (size_t)grow * FDIM + col;
                float4 hv0 = *(const float4*)hp, hv1 = *(const float4*)(hp+4);
                float4 rv0 = *(const float4*)rp, rv1 = *(const float4*)(rp+4);
                v0 = make_float4(hv0.x*rv0.x, hv0.y*rv0.y, hv0.z*rv0.z, hv0.w*rv0.w);
                v1 = make_float4(hv1.x*rv1.x, hv1.y*rv1.y, hv1.z*rv1.z, hv1.w*rv1.w);
            }
        }
        GEMM_STORE_A(v0, v1)
        GEMM_LOAD_W(Lh, kk)
        __syncthreads();
        GEMM_COMPUTE
        __syncthreads();
    }
    float4 b0 = *(const float4*)(lbh + tx * 8);
    float4 b1 = *(const float4*)(lbh + tx * 8 + 4);
    float bb[8] = {b0.x,b0.y,b0.z,b0.w,b1.x,b1.y,b1.z,b1.w};
    #pragma unroll
    for (int i = 0; i < 8; i++) {
        int row = row0 + ty * 8 + i;
        if (row < N_NODES) {
            const float* zp = g_Z + (size_t)row * FDIM + tx * 8;
            const float* hp = H + (size_t)row * FDIM + tx * 8;
            float4 z0 = *(const float4*)zp, z1 = *(const float4*)(zp+4);
            float4 h0 = *(const float4*)hp, h1 = *(const float4*)(hp+4);
            float zz[8] = {z0.x,z0.y,z0.z,z0.w,z1.x,z1.y,z1.z,z1.w};
            float hh[8] = {h0.x,h0.y,h0.z,h0.w,h1.x,h1.y,h1.z,h1.w};
            float hr[8], rl[8];
            #pragma unroll
            for (int j = 0; j < 8; j++) {
                float xv = acc[i][j] + bb[j];
                float t = 1.0f - 2.0f / (__expf(2.0f * xv) + 1.0f);   // tanh
                hr[j] = zz[j] * hh[j] + (1.0f - zz[j]) * t;
                rl[j] = fmaxf(hr[j], 0.0f);
            }
            float* hd = h_out + (size_t)row * FDIM + tx * 8;
            *(float4*)hd = make_float4(hr[0],hr[1],hr[2],hr[3]);
            *(float4*)(hd+4) = make_float4(hr[4],hr[5],hr[6],hr[7]);
            float* rd = relu_s + (size_t)row * FDIM + tx * 8;
            *(float4*)rd = make_float4(rl[0],rl[1],rl[2],rl[3]);
            *(float4*)(rd+4) = make_float4(rl[4],rl[5],rl[6],rl[7]);
        }
    }
}

// ---------------- readout: y = relu(h) @ Wo + bo ------------------------------
__global__ void __launch_bounds__(128)
k_readout(const float* __restrict__ Wo, const float* __restrict__ bo,
          float* __restrict__ y_out) {
    __shared__ float Wos[FDIM * OUTD + OUTD];
    int tid = threadIdx.x;
    for (int t = tid; t < FDIM * OUTD; t += 128) Wos[t] = Wo[t];
    if (tid < OUTD) Wos[FDIM * OUTD + tid] = bo[tid];
    __syncthreads();
    int row = blockIdx.x * 128 + tid;
    if (row >= N_NODES) return;
    const float* hr = g_gate + (size_t)row * FDIM;   // relu(h)
    float acc[OUTD] = {};
    #pragma unroll 4
    for (int k4 = 0; k4 < FDIM / 4; k4++) {
        float4 hv = *(const float4*)(hr + k4 * 4);
        float hvv[4] = {hv.x, hv.y, hv.z, hv.w};
        #pragma unroll
        for (int j = 0; j < 4; j++)
            #pragma unroll
            for (int o = 0; o < OUTD; o++)
                acc[o] += hvv[j] * Wos[(k4 * 4 + j) * OUTD + o];
    }
    #pragma unroll
    for (int o = 0; o < OUTD; o++)
        y_out[(size_t)row * OUTD + o] = acc[o] + Wos[FDIM * OUTD + o];
}

// ---------------- launch ------------------------------------------------------
extern "C" void kernel_launch(void* const* d_in, const int* in_sizes, int n_in,
                              void* d_out, int out_size) {
    const float* x  = (const float*)d_in[0];
    const int*   ei = (const int*)d_in[1];      // edge_index as int32 (harness dtype)
    const float* ew = (const float*)d_in[2];
    const float* H  = (const float*)d_in[3];
    const float* Wz = (const float*)d_in[4];
    const float* bz = (const float*)d_in[5];
    const float* Wr = (const float*)d_in[6];
    const float* br = (const float*)d_in[7];
    const float* Wh = (const float*)d_in[8];
    const float* bh = (const float*)d_in[9];
    const float* Lz = (const float*)d_in[10];
    const float* lbz = (const float*)d_in[11];
    const float* Lr = (const float*)d_in[12];
    const float* lbr = (const float*)d_in[13];
    const float* Lh = (const float*)d_in[14];
    const float* lbh = (const float*)d_in[15];
    const float* Wo = (const float*)d_in[16];
    const float* bo = (const float*)d_in[17];

    float* y_out = (float*)d_out;                           // (N, 12)
    float* h_out = (float*)d_out + (size_t)N_NODES * OUTD;  // (N, 128)

    int nblk = (N_NODES + 127) / 128;   // 391

    k_init_deg<<<(N_NODES + 255) / 256, 256>>>();
    k_deg_acc<<<592, 256>>>(ei, ew);
    k_dinv_self<<<(N_NODES * 32 + 255) / 256, 256>>>(x);
    k_edge_agg<<<(E_EDGES * 32 + 255) / 256, 256>>>(ei, ew, x);
    k_gates_gemm<<<dim3(nblk, 3), 256>>>(Wz, bz, Wr, br, Wh, bh);
    k_zr_gemm<<<dim3(nblk, 2), 256>>>(H, Lz, lbz, Lr, lbr);
    k_final<<<nblk, 256>>>(H, Lh, lbh, h_out);
    k_readout<<<nblk, 128>>>(Wo, bo, y_out);
}

// round 10
// speedup vs baseline: 2.0573x; 1.8456x over previous
#include <cuda_runtime.h>
#include <cstdint>

#define N_NODES 50000
#define E_EDGES 600000
#define FDIM 128
#define OUTD 12

// ---------------- scratch (device globals; no runtime allocation) ------------
__device__ float g_deg[N_NODES];
__device__ float g_dinv[N_NODES];
__device__ float g_agg[(size_t)N_NODES * FDIM];          // A_norm @ x
__device__ float g_gate[(size_t)3 * N_NODES * FDIM];     // gz, gr, gh (gz reused as relu(h))
__device__ float g_Z[(size_t)N_NODES * FDIM];
__device__ float g_R[(size_t)N_NODES * FDIM];

// ---------------- degree / norm (unchanged, measured 79us pipeline) ----------
__global__ void k_init_deg() {
    int i = blockIdx.x * blockDim.x + threadIdx.x;
    if (i < N_NODES) g_deg[i] = 1.0f;
}

__global__ void k_deg_acc(const int* __restrict__ ei,
                          const float* __restrict__ ew) {
    for (int e = blockIdx.x * blockDim.x + threadIdx.x; e < E_EDGES;
         e += gridDim.x * blockDim.x) {
        int d = ei[E_EDGES + e];
        atomicAdd(&g_deg[d], ew[e]);
    }
}

__global__ void k_dinv_self(const float* __restrict__ x) {
    int warp = (blockIdx.x * blockDim.x + threadIdx.x) >> 5;
    int lane = threadIdx.x & 31;
    if (warp >= N_NODES) return;
    float s;
    if (lane == 0) {
        float dg = g_deg[warp];
        s = (dg > 0.0f) ? rsqrtf(dg) : 0.0f;
        g_dinv[warp] = s;
    }
    s = __shfl_sync(0xffffffffu, s, 0);
    float s2 = s * s;
    size_t off = (size_t)warp * FDIM + lane * 4;
    float4 v = *(const float4*)(x + off);
    v.x *= s2; v.y *= s2; v.z *= s2; v.w *= s2;
    *(float4*)(g_agg + off) = v;
}

__global__ void k_edge_agg(const int* __restrict__ ei,
                           const float* __restrict__ ew,
                           const float* __restrict__ x) {
    int warp = (blockIdx.x * blockDim.x + threadIdx.x) >> 5;
    int lane = threadIdx.x & 31;
    if (warp >= E_EDGES) return;
    int s = 0, d = 0;
    float norm = 0.0f;
    if (lane == 0) {
        s = ei[warp];
        d = ei[E_EDGES + warp];
        norm = g_dinv[s] * ew[warp] * g_dinv[d];
    }
    s = __shfl_sync(0xffffffffu, s, 0);
    d = __shfl_sync(0xffffffffu, d, 0);
    norm = __shfl_sync(0xffffffffu, norm, 0);
    float4 v = *(const float4*)(x + (size_t)s * FDIM + lane * 4);
    float* p = g_agg + (size_t)d * FDIM + lane * 4;
    asm volatile("red.global.add.v4.f32 [%0], {%1,%2,%3,%4};"
                 :: "l"(p), "f"(v.x * norm), "f"(v.y * norm),
                    "f"(v.z * norm), "f"(v.w * norm)
                 : "memory");
}

// ===================== tf32 tensor-core GEMM machinery ========================
// Block: 128 rows x 128 cols, 256 threads = 8 warps as 2(row) x 4(col),
// warp tile 64x32 = 4 m-tiles x 4 n-tiles of m16n8k8.
// As[128][36] (bank = 4r+c, conflict-free), Ws[32][136] (bank = 8k+n, c-f).

__device__ __forceinline__ unsigned f2tf(float f) {
    unsigned r; asm("cvt.rna.tf32.f32 %0, %1;" : "=r"(r) : "f"(f)); return r;
}

__device__ __forceinline__ void mma8(float* c, unsigned a0, unsigned a1,
                                     unsigned a2, unsigned a3,
                                     unsigned b0, unsigned b1) {
    asm volatile("mma.sync.aligned.m16n8k8.row.col.f32.tf32.tf32.f32 "
        "{%0,%1,%2,%3},{%4,%5,%6,%7},{%8,%9},{%0,%1,%2,%3};"
        : "+f"(c[0]), "+f"(c[1]), "+f"(c[2]), "+f"(c[3])
        : "r"(a0), "r"(a1), "r"(a2), "r"(a3), "r"(b0), "r"(b1));
}

#define TC_DECL                                                            \
    __shared__ unsigned As[128][36];                                       \
    __shared__ unsigned Ws[32][136];                                       \
    int tid = threadIdx.x;                                                 \
    int lane = tid & 31, wid = tid >> 5;                                   \
    int qid = lane >> 2, qtid = lane & 3;                                  \
    int wr = (wid >> 2) * 64, wc = (wid & 3) * 32;                         \
    int row0 = blockIdx.x * 128;                                           \
    float acc[4][4][4] = {};

// load+convert one 32x128 W chunk
#define TC_LOAD_W(Wsrc, kk)                                                \
    _Pragma("unroll")                                                      \
    for (int t = 0; t < 4; t++) {                                          \
        int idx = tid + t * 256;                                           \
        int r = idx >> 5, c = (idx & 31) * 4;                              \
        float4 v = *(const float4*)((Wsrc) + (size_t)((kk) + r) * FDIM + c); \
        *(uint4*)&Ws[r][c] = make_uint4(f2tf(v.x), f2tf(v.y), f2tf(v.z), f2tf(v.w)); \
    }

// store one float4 of A (already in v) into As at row r, col c (tf32)
#define TC_STORE_A(r, c, v)                                                \
    *(uint4*)&As[r][c] = make_uint4(f2tf((v).x), f2tf((v).y), f2tf((v).z), f2tf((v).w));

#define TC_COMPUTE                                                         \
    _Pragma("unroll")                                                      \
    for (int ks = 0; ks < 32; ks += 8) {                                   \
        unsigned af[4][4], bf[4][2];                                       \
        _Pragma("unroll")                                                  \
        for (int m = 0; m < 4; m++) {                                      \
            int r = wr + 16 * m + qid;                                     \
            af[m][0] = As[r][ks + qtid];                                   \
            af[m][1] = As[r + 8][ks + qtid];                               \
            af[m][2] = As[r][ks + qtid + 4];                               \
            af[m][3] = As[r + 8][ks + qtid + 4];                           \
        }                                                                  \
        _Pragma("unroll")                                                  \
        for (int n = 0; n < 4; n++) {                                      \
            int cc = wc + 8 * n + qid;                                     \
            bf[n][0] = Ws[ks + qtid][cc];                                  \
            bf[n][1] = Ws[ks + qtid + 4][cc];                              \
        }                                                                  \
        _Pragma("unroll")                                                  \
        for (int m = 0; m < 4; m++)                                        \
            _Pragma("unroll")                                              \
            for (int n = 0; n < 4; n++)                                    \
                mma8(acc[m][n], af[m][0], af[m][1], af[m][2], af[m][3],    \
                     bf[n][0], bf[n][1]);                                  \
    }

// ---------------- GEMM 1: gz/gr/gh = agg @ W + b (blockIdx.y = gate) ---------
__global__ void __launch_bounds__(256, 2)
k_gates_gemm(const float* __restrict__ Wz, const float* __restrict__ bz,
             const float* __restrict__ Wr, const float* __restrict__ br,
             const float* __restrict__ Wh, const float* __restrict__ bh) {
    int gate = blockIdx.y;
    const float* W = (gate == 0) ? Wz : (gate == 1) ? Wr : Wh;
    const float* b = (gate == 0) ? bz : (gate == 1) ? br : bh;
    float* C = g_gate + (size_t)gate * N_NODES * FDIM;

    TC_DECL
    for (int kk = 0; kk < 128; kk += 32) {
        #pragma unroll
        for (int t = 0; t < 4; t++) {
            int idx = tid + t * 256;
            int r = idx >> 3, c = (idx & 7) * 4;
            float4 v = make_float4(0.f, 0.f, 0.f, 0.f);
            if (row0 + r < N_NODES)
                v = *(const float4*)(g_agg + (size_t)(row0 + r) * FDIM + kk + c);
            TC_STORE_A(r, c, v)
        }
        TC_LOAD_W(W, kk)
        __syncthreads();
        TC_COMPUTE
        __syncthreads();
    }
    #pragma unroll
    for (int m = 0; m < 4; m++) {
        #pragma unroll
        for (int n = 0; n < 4; n++) {
            int col = wc + 8 * n + 2 * qtid;
            float b0v = b[col], b1v = b[col + 1];
            #pragma unroll
            for (int h = 0; h < 2; h++) {
                int row = row0 + wr + 16 * m + qid + 8 * h;
                if (row < N_NODES) {
                    float2 o = make_float2(acc[m][n][2 * h] + b0v,
                                           acc[m][n][2 * h + 1] + b1v);
                    *(float2*)(C + (size_t)row * FDIM + col) = o;
                }
            }
        }
    }
}

// ---------------- GEMM 2: Z = sig([gz,H]@Lz+lbz), R = sig([gr,H]@Lr+lbr) -----
__global__ void __launch_bounds__(256, 2)
k_zr_gemm(const float* __restrict__ H,
          const float* __restrict__ Lz, const float* __restrict__ lbz,
          const float* __restrict__ Lr, const float* __restrict__ lbr) {
    int which = blockIdx.y;
    const float* G = g_gate + (size_t)which * N_NODES * FDIM;
    const float* L = (which == 0) ? Lz : Lr;
    const float* lb = (which == 0) ? lbz : lbr;
    float* C = (which == 0) ? g_Z : g_R;

    TC_DECL
    for (int kk = 0; kk < 256; kk += 32) {
        const float* Asrc = (kk < 128) ? G : H;
        int colbase = kk & 127;
        #pragma unroll
        for (int t = 0; t < 4; t++) {
            int idx = tid + t * 256;
            int r = idx >> 3, c = (idx & 7) * 4;
            float4 v = make_float4(0.f, 0.f, 0.f, 0.f);
            if (row0 + r < N_NODES)
                v = *(const float4*)(Asrc + (size_t)(row0 + r) * FDIM + colbase + c);
            TC_STORE_A(r, c, v)
        }
        TC_LOAD_W(L, kk)
        __syncthreads();
        TC_COMPUTE
        __syncthreads();
    }
    #pragma unroll
    for (int m = 0; m < 4; m++) {
        #pragma unroll
        for (int n = 0; n < 4; n++) {
            int col = wc + 8 * n + 2 * qtid;
            float b0v = lb[col], b1v = lb[col + 1];
            #pragma unroll
            for (int h = 0; h < 2; h++) {
                int row = row0 + wr + 16 * m + qid + 8 * h;
                if (row < N_NODES) {
                    float2 o;
                    o.x = 1.0f / (1.0f + __expf(-(acc[m][n][2 * h] + b0v)));
                    o.y = 1.0f / (1.0f + __expf(-(acc[m][n][2 * h + 1] + b1v)));
                    *(float2*)(C + (size_t)row * FDIM + col) = o;
                }
            }
        }
    }
}

// ------ GEMM 3: Ht = tanh([gh, H*R]@Lh+lbh); h = Z*H+(1-Z)*Ht ----------------
__global__ void __launch_bounds__(256, 2)
k_final(const float* __restrict__ H,
        const float* __restrict__ Lh, const float* __restrict__ lbh,
        float* __restrict__ h_out) {
    const float* Gh = g_gate + (size_t)2 * N_NODES * FDIM;
    float* relu_s = g_gate;   // scratch reuse (gz consumed)

    TC_DECL
    for (int kk = 0; kk < 256; kk += 32) {
        #pragma unroll
        for (int t = 0; t < 4; t++) {
            int idx = tid + t * 256;
            int r = idx >> 3, c = (idx & 7) * 4;
            float4 v = make_float4(0.f, 0.f, 0.f, 0.f);
            if (row0 + r < N_NODES) {
                if (kk < 128) {
                    v = *(const float4*)(Gh + (size_t)(row0 + r) * FDIM + kk + c);
                } else {
                    int col = kk - 128 + c;
                    float4 hv = *(const float4*)(H + (size_t)(row0 + r) * FDIM + col);
                    float4 rv = *(const float4*)(g_R + (size_t)(row0 + r) * FDIM + col);
                    v = make_float4(hv.x * rv.x, hv.y * rv.y, hv.z * rv.z, hv.w * rv.w);
                }
            }
            TC_STORE_A(r, c, v)
        }
        TC_LOAD_W(Lh, kk)
        __syncthreads();
        TC_COMPUTE
        __syncthreads();
    }
    #pragma unroll
    for (int m = 0; m < 4; m++) {
        #pragma unroll
        for (int n = 0; n < 4; n++) {
            int col = wc + 8 * n + 2 * qtid;
            float b0v = lbh[col], b1v = lbh[col + 1];
            #pragma unroll
            for (int h = 0; h < 2; h++) {
                int row = row0 + wr + 16 * m + qid + 8 * h;
                if (row < N_NODES) {
                    float2 zv = *(const float2*)(g_Z + (size_t)row * FDIM + col);
                    float2 hv = *(const float2*)(H + (size_t)row * FDIM + col);
                    float x0 = acc[m][n][2 * h] + b0v;
                    float x1 = acc[m][n][2 * h + 1] + b1v;
                    float t0 = 1.0f - 2.0f / (__expf(2.0f * x0) + 1.0f);
                    float t1 = 1.0f - 2.0f / (__expf(2.0f * x1) + 1.0f);
                    float2 hr;
                    hr.x = zv.x * hv.x + (1.0f - zv.x) * t0;
                    hr.y = zv.y * hv.y + (1.0f - zv.y) * t1;
                    *(float2*)(h_out + (size_t)row * FDIM + col) = hr;
                    float2 rl = make_float2(fmaxf(hr.x, 0.0f), fmaxf(hr.y, 0.0f));
                    *(float2*)(relu_s + (size_t)row * FDIM + col) = rl;
                }
            }
        }
    }
}

// ---------------- readout: y = relu(h) @ Wo + bo ------------------------------
__global__ void __launch_bounds__(128)
k_readout(const float* __restrict__ Wo, const float* __restrict__ bo,
          float* __restrict__ y_out) {
    __shared__ float Wos[FDIM * OUTD + OUTD];
    int tid = threadIdx.x;
    for (int t = tid; t < FDIM * OUTD; t += 128) Wos[t] = Wo[t];
    if (tid < OUTD) Wos[FDIM * OUTD + tid] = bo[tid];
    __syncthreads();
    int row = blockIdx.x * 128 + tid;
    if (row >= N_NODES) return;
    const float* hr = g_gate + (size_t)row * FDIM;   // relu(h)
    float acc[OUTD] = {};
    #pragma unroll 4
    for (int k4 = 0; k4 < FDIM / 4; k4++) {
        float4 hv = *(const float4*)(hr + k4 * 4);
        float hvv[4] = {hv.x, hv.y, hv.z, hv.w};
        #pragma unroll
        for (int j = 0; j < 4; j++)
            #pragma unroll
            for (int o = 0; o < OUTD; o++)
                acc[o] += hvv[j] * Wos[(k4 * 4 + j) * OUTD + o];
    }
    #pragma unroll
    for (int o = 0; o < OUTD; o++)
        y_out[(size_t)row * OUTD + o] = acc[o] + Wos[FDIM * OUTD + o];
}

// ---------------- launch ------------------------------------------------------
extern "C" void kernel_launch(void* const* d_in, const int* in_sizes, int n_in,
                              void* d_out, int out_size) {
    const float* x  = (const float*)d_in[0];
    const int*   ei = (const int*)d_in[1];
    const float* ew = (const float*)d_in[2];
    const float* H  = (const float*)d_in[3];
    const float* Wz = (const float*)d_in[4];
    const float* bz = (const float*)d_in[5];
    const float* Wr = (const float*)d_in[6];
    const float* br = (const float*)d_in[7];
    const float* Wh = (const float*)d_in[8];
    const float* bh = (const float*)d_in[9];
    const float* Lz = (const float*)d_in[10];
    const float* lbz = (const float*)d_in[11];
    const float* Lr = (const float*)d_in[12];
    const float* lbr = (const float*)d_in[13];
    const float* Lh = (const float*)d_in[14];
    const float* lbh = (const float*)d_in[15];
    const float* Wo = (const float*)d_in[16];
    const float* bo = (const float*)d_in[17];

    float* y_out = (float*)d_out;                           // (N, 12)
    float* h_out = (float*)d_out + (size_t)N_NODES * OUTD;  // (N, 128)

    int nblk = (N_NODES + 127) / 128;   // 391

    k_init_deg<<<(N_NODES + 255) / 256, 256>>>();
    k_deg_acc<<<592, 256>>>(ei, ew);
    k_dinv_self<<<(N_NODES * 32 + 255) / 256, 256>>>(x);
    k_edge_agg<<<(E_EDGES * 32 + 255) / 256, 256>>>(ei, ew, x);
    k_gates_gemm<<<dim3(nblk, 3), 256>>>(Wz, bz, Wr, br, Wh, bh);
    k_zr_gemm<<<dim3(nblk, 2), 256>>>(H, Lz, lbz, Lr, lbr);
    k_final<<<nblk, 256>>>(H, Lh, lbh, h_out);
    k_readout<<<nblk, 128>>>(Wo, bo, y_out);
}

// round 11
// speedup vs baseline: 2.2057x; 1.0721x over previous
#include <cuda_runtime.h>
#include <cstdint>

#define N_NODES 50000
#define E_EDGES 600000
#define FDIM 128
#define OUTD 12

// ---------------- scratch (device globals; no runtime allocation) ------------
__device__ float g_deg[N_NODES];
__device__ float g_dinv[N_NODES];
__device__ float g_agg[(size_t)N_NODES * FDIM];          // A_norm @ x
__device__ float g_Z[(size_t)N_NODES * FDIM];
__device__ float g_R[(size_t)N_NODES * FDIM];
__device__ float g_relu[(size_t)N_NODES * FDIM];         // relu(h)
__device__ float g_Wcomb[3][256 * FDIM];                 // [Mg ; Lg_bot] per gate
__device__ float g_c[3][FDIM];                           // folded biases

// ---------------- weight folding: Mg = Wg @ Lg_top ----------------------------
// grid (2, 3): 64-row tile per block, SIMT fp32 (tiny: 1M FMA/block)
__global__ void __launch_bounds__(256)
k_prep_m(const float* __restrict__ Wz, const float* __restrict__ Wr,
         const float* __restrict__ Wh, const float* __restrict__ Lz,
         const float* __restrict__ Lr, const float* __restrict__ Lh) {
    int gate = blockIdx.y;
    const float* W = (gate == 0) ? Wz : (gate == 1) ? Wr : Wh;
    const float* L = (gate == 0) ? Lz : (gate == 1) ? Lr : Lh;
    float* C = g_Wcomb[gate];

    __shared__ float As[64][16];
    __shared__ float Ls[16][128];
    int tid = threadIdx.x, tx = tid & 31, ty = tid >> 5;
    int row0 = blockIdx.x * 64;
    float acc[8][4] = {};

    for (int kk = 0; kk < 128; kk += 16) {
        {
            int r = tid >> 2, c4 = tid & 3;
            *(float4*)&As[r][c4 * 4] =
                *(const float4*)(W + (size_t)(row0 + r) * FDIM + kk + c4 * 4);
        }
        #pragma unroll
        for (int t = 0; t < 2; t++) {
            int idx = tid + t * 256;
            int r = idx >> 5, c = (idx & 31) * 4;
            *(float4*)&Ls[r][c] = *(const float4*)(L + (size_t)(kk + r) * FDIM + c);
        }
        __syncthreads();
        #pragma unroll
        for (int k = 0; k < 16; k++) {
            float4 wv = *(float4*)&Ls[k][tx * 4];
            #pragma unroll
            for (int i = 0; i < 8; i++) {
                float a = As[ty * 8 + i][k];
                acc[i][0] += a * wv.x; acc[i][1] += a * wv.y;
                acc[i][2] += a * wv.z; acc[i][3] += a * wv.w;
            }
        }
        __syncthreads();
    }
    #pragma unroll
    for (int i = 0; i < 8; i++) {
        int row = row0 + ty * 8 + i;
        *(float4*)(C + (size_t)row * FDIM + tx * 4) =
            make_float4(acc[i][0], acc[i][1], acc[i][2], acc[i][3]);
    }
}

// copy Lg_bot into comb rows 128..255; fold bias c = b@Lg_top + lb. grid(3)
__global__ void __launch_bounds__(256)
k_prep_rest(const float* __restrict__ Lz, const float* __restrict__ Lr,
            const float* __restrict__ Lh,
            const float* __restrict__ bz, const float* __restrict__ br,
            const float* __restrict__ bh,
            const float* __restrict__ lbz, const float* __restrict__ lbr,
            const float* __restrict__ lbh) {
    int g = blockIdx.x;
    const float* L  = (g == 0) ? Lz : (g == 1) ? Lr : Lh;
    const float* b  = (g == 0) ? bz : (g == 1) ? br : bh;
    const float* lb = (g == 0) ? lbz : (g == 1) ? lbr : lbh;
    float* C = g_Wcomb[g];
    int tid = threadIdx.x;
    for (int i = tid; i < 128 * FDIM / 4; i += 256)
        ((float4*)(C + 128 * FDIM))[i] = ((const float4*)(L + 128 * FDIM))[i];
    if (tid < FDIM) {
        float a = lb[tid];
        #pragma unroll 8
        for (int k = 0; k < 128; k++) a += b[k] * L[(size_t)k * FDIM + tid];
        g_c[g][tid] = a;
    }
}

// ---------------- degree / norm / aggregation (measured ~85us) ----------------
__global__ void k_init_deg() {
    int i = blockIdx.x * blockDim.x + threadIdx.x;
    if (i < N_NODES) g_deg[i] = 1.0f;
}

__global__ void k_deg_acc(const int* __restrict__ ei,
                          const float* __restrict__ ew) {
    for (int e = blockIdx.x * blockDim.x + threadIdx.x; e < E_EDGES;
         e += gridDim.x * blockDim.x) {
        int d = ei[E_EDGES + e];
        atomicAdd(&g_deg[d], ew[e]);
    }
}

__global__ void k_dinv_self(const float* __restrict__ x) {
    int warp = (blockIdx.x * blockDim.x + threadIdx.x) >> 5;
    int lane = threadIdx.x & 31;
    if (warp >= N_NODES) return;
    float s;
    if (lane == 0) {
        float dg = g_deg[warp];
        s = (dg > 0.0f) ? rsqrtf(dg) : 0.0f;
        g_dinv[warp] = s;
    }
    s = __shfl_sync(0xffffffffu, s, 0);
    float s2 = s * s;
    size_t off = (size_t)warp * FDIM + lane * 4;
    float4 v = *(const float4*)(x + off);
    v.x *= s2; v.y *= s2; v.z *= s2; v.w *= s2;
    *(float4*)(g_agg + off) = v;
}

__global__ void k_edge_agg(const int* __restrict__ ei,
                           const float* __restrict__ ew,
                           const float* __restrict__ x) {
    int warp = (blockIdx.x * blockDim.x + threadIdx.x) >> 5;
    int lane = threadIdx.x & 31;
    if (warp >= E_EDGES) return;
    int s = 0, d = 0;
    float norm = 0.0f;
    if (lane == 0) {
        s = ei[warp];
        d = ei[E_EDGES + warp];
        norm = g_dinv[s] * ew[warp] * g_dinv[d];
    }
    s = __shfl_sync(0xffffffffu, s, 0);
    d = __shfl_sync(0xffffffffu, d, 0);
    norm = __shfl_sync(0xffffffffu, norm, 0);
    float4 v = *(const float4*)(x + (size_t)s * FDIM + lane * 4);
    float* p = g_agg + (size_t)d * FDIM + lane * 4;
    asm volatile("red.global.add.v4.f32 [%0], {%1,%2,%3,%4};"
                 :: "l"(p), "f"(v.x * norm), "f"(v.y * norm),
                    "f"(v.z * norm), "f"(v.w * norm)
                 : "memory");
}

// ===================== tf32 tensor-core GEMM machinery ========================
__device__ __forceinline__ unsigned f2tf(float f) {
    unsigned r; asm("cvt.rna.tf32.f32 %0, %1;" : "=r"(r) : "f"(f)); return r;
}

__device__ __forceinline__ void mma8(float* c, unsigned a0, unsigned a1,
                                     unsigned a2, unsigned a3,
                                     unsigned b0, unsigned b1) {
    asm volatile("mma.sync.aligned.m16n8k8.row.col.f32.tf32.tf32.f32 "
        "{%0,%1,%2,%3},{%4,%5,%6,%7},{%8,%9},{%0,%1,%2,%3};"
        : "+f"(c[0]), "+f"(c[1]), "+f"(c[2]), "+f"(c[3])
        : "r"(a0), "r"(a1), "r"(a2), "r"(a3), "r"(b0), "r"(b1));
}

#define TC_DECL                                                            \
    __shared__ unsigned As[128][36];                                       \
    __shared__ unsigned Ws[32][136];                                       \
    int tid = threadIdx.x;                                                 \
    int lane = tid & 31, wid = tid >> 5;                                   \
    int qid = lane >> 2, qtid = lane & 3;                                  \
    int wr = (wid >> 2) * 64, wc = (wid & 3) * 32;                         \
    int row0 = blockIdx.x * 128;                                           \
    float acc[4][4][4] = {};

#define TC_LOAD_W(Wsrc, kk)                                                \
    _Pragma("unroll")                                                      \
    for (int t = 0; t < 4; t++) {                                          \
        int idx = tid + t * 256;                                           \
        int r = idx >> 5, c = (idx & 31) * 4;                              \
        float4 v = *(const float4*)((Wsrc) + (size_t)((kk) + r) * FDIM + c); \
        *(uint4*)&Ws[r][c] = make_uint4(f2tf(v.x), f2tf(v.y), f2tf(v.z), f2tf(v.w)); \
    }

#define TC_STORE_A(r, c, v)                                                \
    *(uint4*)&As[r][c] = make_uint4(f2tf((v).x), f2tf((v).y), f2tf((v).z), f2tf((v).w));

#define TC_COMPUTE                                                         \
    _Pragma("unroll")                                                      \
    for (int ks = 0; ks < 32; ks += 8) {                                   \
        unsigned af[4][4], bf[4][2];                                       \
        _Pragma("unroll")                                                  \
        for (int m = 0; m < 4; m++) {                                      \
            int r = wr + 16 * m + qid;                                     \
            af[m][0] = As[r][ks + qtid];                                   \
            af[m][1] = As[r + 8][ks + qtid];                               \
            af[m][2] = As[r][ks + qtid + 4];                               \
            af[m][3] = As[r + 8][ks + qtid + 4];                           \
        }                                                                  \
        _Pragma("unroll")                                                  \
        for (int n = 0; n < 4; n++) {                                      \
            int cc = wc + 8 * n + qid;                                     \
            bf[n][0] = Ws[ks + qtid][cc];                                  \
            bf[n][1] = Ws[ks + qtid + 4][cc];                              \
        }                                                                  \
        _Pragma("unroll")                                                  \
        for (int m = 0; m < 4; m++)                                        \
            _Pragma("unroll")                                              \
            for (int n = 0; n < 4; n++)                                    \
                mma8(acc[m][n], af[m][0], af[m][1], af[m][2], af[m][3],    \
                     bf[n][0], bf[n][1]);                                  \
    }

// ------- GEMM A: Z/R = sigmoid(agg@Mg + H@Pg + cg)  (blockIdx.y = gate) ------
__global__ void __launch_bounds__(256, 2)
k_zr_gemm(const float* __restrict__ H) {
    int which = blockIdx.y;          // 0=Z, 1=R
    const float* Wc = g_Wcomb[which];
    const float* cb = g_c[which];
    float* C = (which == 0) ? g_Z : g_R;

    TC_DECL
    for (int kk = 0; kk < 256; kk += 32) {
        const float* Asrc = (kk < 128) ? g_agg : H;
        int colbase = kk & 127;
        #pragma unroll
        for (int t = 0; t < 4; t++) {
            int idx = tid + t * 256;
            int r = idx >> 3, c = (idx & 7) * 4;
            float4 v = make_float4(0.f, 0.f, 0.f, 0.f);
            if (row0 + r < N_NODES)
                v = *(const float4*)(Asrc + (size_t)(row0 + r) * FDIM + colbase + c);
            TC_STORE_A(r, c, v)
        }
        TC_LOAD_W(Wc, kk)
        __syncthreads();
        TC_COMPUTE
        __syncthreads();
    }
    #pragma unroll
    for (int m = 0; m < 4; m++) {
        #pragma unroll
        for (int n = 0; n < 4; n++) {
            int col = wc + 8 * n + 2 * qtid;
            float b0v = cb[col], b1v = cb[col + 1];
            #pragma unroll
            for (int h = 0; h < 2; h++) {
                int row = row0 + wr + 16 * m + qid + 8 * h;
                if (row < N_NODES) {
                    float2 o;
                    o.x = 1.0f / (1.0f + __expf(-(acc[m][n][2 * h] + b0v)));
                    o.y = 1.0f / (1.0f + __expf(-(acc[m][n][2 * h + 1] + b1v)));
                    *(float2*)(C + (size_t)row * FDIM + col) = o;
                }
            }
        }
    }
}

// ------ GEMM B: Ht = tanh(agg@Mh + (H*R)@Ph + ch); h = Z*H+(1-Z)*Ht ----------
__global__ void __launch_bounds__(256, 2)
k_final(const float* __restrict__ H, float* __restrict__ h_out) {
    const float* Wc = g_Wcomb[2];
    const float* cb = g_c[2];

    TC_DECL
    for (int kk = 0; kk < 256; kk += 32) {
        #pragma unroll
        for (int t = 0; t < 4; t++) {
            int idx = tid + t * 256;
            int r = idx >> 3, c = (idx & 7) * 4;
            float4 v = make_float4(0.f, 0.f, 0.f, 0.f);
            if (row0 + r < N_NODES) {
                if (kk < 128) {
                    v = *(const float4*)(g_agg + (size_t)(row0 + r) * FDIM + kk + c);
                } else {
                    int col = kk - 128 + c;
                    float4 hv = *(const float4*)(H + (size_t)(row0 + r) * FDIM + col);
                    float4 rv = *(const float4*)(g_R + (size_t)(row0 + r) * FDIM + col);
                    v = make_float4(hv.x * rv.x, hv.y * rv.y, hv.z * rv.z, hv.w * rv.w);
                }
            }
            TC_STORE_A(r, c, v)
        }
        TC_LOAD_W(Wc, kk)
        __syncthreads();
        TC_COMPUTE
        __syncthreads();
    }
    #pragma unroll
    for (int m = 0; m < 4; m++) {
        #pragma unroll
        for (int n = 0; n < 4; n++) {
            int col = wc + 8 * n + 2 * qtid;
            float b0v = cb[col], b1v = cb[col + 1];
            #pragma unroll
            for (int h = 0; h < 2; h++) {
                int row = row0 + wr + 16 * m + qid + 8 * h;
                if (row < N_NODES) {
                    float2 zv = *(const float2*)(g_Z + (size_t)row * FDIM + col);
                    float2 hv = *(const float2*)(H + (size_t)row * FDIM + col);
                    float x0 = acc[m][n][2 * h] + b0v;
                    float x1 = acc[m][n][2 * h + 1] + b1v;
                    float t0 = 1.0f - 2.0f / (__expf(2.0f * x0) + 1.0f);
                    float t1 = 1.0f - 2.0f / (__expf(2.0f * x1) + 1.0f);
                    float2 hr;
                    hr.x = zv.x * hv.x + (1.0f - zv.x) * t0;
                    hr.y = zv.y * hv.y + (1.0f - zv.y) * t1;
                    *(float2*)(h_out + (size_t)row * FDIM + col) = hr;
                    float2 rl = make_float2(fmaxf(hr.x, 0.0f), fmaxf(hr.y, 0.0f));
                    *(float2*)(g_relu + (size_t)row * FDIM + col) = rl;
                }
            }
        }
    }
}

// ---------------- readout: y = relu(h) @ Wo + bo ------------------------------
__global__ void __launch_bounds__(128)
k_readout(const float* __restrict__ Wo, const float* __restrict__ bo,
          float* __restrict__ y_out) {
    __shared__ float Wos[FDIM * OUTD + OUTD];
    int tid = threadIdx.x;
    for (int t = tid; t < FDIM * OUTD; t += 128) Wos[t] = Wo[t];
    if (tid < OUTD) Wos[FDIM * OUTD + tid] = bo[tid];
    __syncthreads();
    int row = blockIdx.x * 128 + tid;
    if (row >= N_NODES) return;
    const float* hr = g_relu + (size_t)row * FDIM;
    float acc[OUTD] = {};
    #pragma unroll 4
    for (int k4 = 0; k4 < FDIM / 4; k4++) {
        float4 hv = *(const float4*)(hr + k4 * 4);
        float hvv[4] = {hv.x, hv.y, hv.z, hv.w};
        #pragma unroll
        for (int j = 0; j < 4; j++)
            #pragma unroll
            for (int o = 0; o < OUTD; o++)
                acc[o] += hvv[j] * Wos[(k4 * 4 + j) * OUTD + o];
    }
    #pragma unroll
    for (int o = 0; o < OUTD; o++)
        y_out[(size_t)row * OUTD + o] = acc[o] + Wos[FDIM * OUTD + o];
}

// ---------------- launch ------------------------------------------------------
extern "C" void kernel_launch(void* const* d_in, const int* in_sizes, int n_in,
                              void* d_out, int out_size) {
    const float* x  = (const float*)d_in[0];
    const int*   ei = (const int*)d_in[1];
    const float* ew = (const float*)d_in[2];
    const float* H  = (const float*)d_in[3];
    const float* Wz = (const float*)d_in[4];
    const float* bz = (const float*)d_in[5];
    const float* Wr = (const float*)d_in[6];
    const float* br = (const float*)d_in[7];
    const float* Wh = (const float*)d_in[8];
    const float* bh = (const float*)d_in[9];
    const float* Lz = (const float*)d_in[10];
    const float* lbz = (const float*)d_in[11];
    const float* Lr = (const float*)d_in[12];
    const float* lbr = (const float*)d_in[13];
    const float* Lh = (const float*)d_in[14];
    const float* lbh = (const float*)d_in[15];
    const float* Wo = (const float*)d_in[16];
    const float* bo = (const float*)d_in[17];

    float* y_out = (float*)d_out;                           // (N, 12)
    float* h_out = (float*)d_out + (size_t)N_NODES * OUTD;  // (N, 128)

    int nblk = (N_NODES + 127) / 128;   // 391

    k_prep_m<<<dim3(2, 3), 256>>>(Wz, Wr, Wh, Lz, Lr, Lh);
    k_prep_rest<<<3, 256>>>(Lz, Lr, Lh, bz, br, bh, lbz, lbr, lbh);
    k_init_deg<<<(N_NODES + 255) / 256, 256>>>();
    k_deg_acc<<<592, 256>>>(ei, ew);
    k_dinv_self<<<(N_NODES * 32 + 255) / 256, 256>>>(x);
    k_edge_agg<<<(E_EDGES * 32 + 255) / 256, 256>>>(ei, ew, x);
    k_zr_gemm<<<dim3(nblk, 2), 256>>>(H);
    k_final<<<nblk, 256>>>(H, h_out);
    k_readout<<<nblk, 128>>>(Wo, bo, y_out);
}

// round 12
// speedup vs baseline: 2.2696x; 1.0290x over previous
#include <cuda_runtime.h>
#include <cstdint>

#define N_NODES 50000
#define E_EDGES 600000
#define FDIM 128
#define OUTD 12

// ---------------- scratch (device globals; no runtime allocation) ------------
__device__ float g_deg[N_NODES];
__device__ float g_dinv[N_NODES];
__device__ float g_agg[(size_t)N_NODES * FDIM];          // A_norm @ x
__device__ float g_Z[(size_t)N_NODES * FDIM];
__device__ float g_R[(size_t)N_NODES * FDIM];            // stores H*R (fused)
__device__ float g_relu[(size_t)N_NODES * FDIM];         // relu(h)
__device__ float g_Wcomb[3][256 * FDIM];                 // [Mg ; Lg_bot] per gate
__device__ float g_c[3][FDIM];                           // folded biases

// ---------------- weight folding: Mg = Wg @ Lg_top ----------------------------
__global__ void __launch_bounds__(256)
k_prep_m(const float* __restrict__ Wz, const float* __restrict__ Wr,
         const float* __restrict__ Wh, const float* __restrict__ Lz,
         const float* __restrict__ Lr, const float* __restrict__ Lh) {
    int gate = blockIdx.y;
    const float* W = (gate == 0) ? Wz : (gate == 1) ? Wr : Wh;
    const float* L = (gate == 0) ? Lz : (gate == 1) ? Lr : Lh;
    float* C = g_Wcomb[gate];

    __shared__ float As[64][16];
    __shared__ float Ls[16][128];
    int tid = threadIdx.x, tx = tid & 31, ty = tid >> 5;
    int row0 = blockIdx.x * 64;
    float acc[8][4] = {};

    for (int kk = 0; kk < 128; kk += 16) {
        {
            int r = tid >> 2, c4 = tid & 3;
            *(float4*)&As[r][c4 * 4] =
                *(const float4*)(W + (size_t)(row0 + r) * FDIM + kk + c4 * 4);
        }
        #pragma unroll
        for (int t = 0; t < 2; t++) {
            int idx = tid + t * 256;
            int r = idx >> 5, c = (idx & 31) * 4;
            *(float4*)&Ls[r][c] = *(const float4*)(L + (size_t)(kk + r) * FDIM + c);
        }
        __syncthreads();
        #pragma unroll
        for (int k = 0; k < 16; k++) {
            float4 wv = *(float4*)&Ls[k][tx * 4];
            #pragma unroll
            for (int i = 0; i < 8; i++) {
                float a = As[ty * 8 + i][k];
                acc[i][0] += a * wv.x; acc[i][1] += a * wv.y;
                acc[i][2] += a * wv.z; acc[i][3] += a * wv.w;
            }
        }
        __syncthreads();
    }
    #pragma unroll
    for (int i = 0; i < 8; i++) {
        int row = row0 + ty * 8 + i;
        *(float4*)(C + (size_t)row * FDIM + tx * 4) =
            make_float4(acc[i][0], acc[i][1], acc[i][2], acc[i][3]);
    }
}

__global__ void __launch_bounds__(256)
k_prep_rest(const float* __restrict__ Lz, const float* __restrict__ Lr,
            const float* __restrict__ Lh,
            const float* __restrict__ bz, const float* __restrict__ br,
            const float* __restrict__ bh,
            const float* __restrict__ lbz, const float* __restrict__ lbr,
            const float* __restrict__ lbh) {
    int g = blockIdx.x;
    const float* L  = (g == 0) ? Lz : (g == 1) ? Lr : Lh;
    const float* b  = (g == 0) ? bz : (g == 1) ? br : bh;
    const float* lb = (g == 0) ? lbz : (g == 1) ? lbr : lbh;
    float* C = g_Wcomb[g];
    int tid = threadIdx.x;
    for (int i = tid; i < 128 * FDIM / 4; i += 256)
        ((float4*)(C + 128 * FDIM))[i] = ((const float4*)(L + 128 * FDIM))[i];
    if (tid < FDIM) {
        float a = lb[tid];
        #pragma unroll 8
        for (int k = 0; k < 128; k++) a += b[k] * L[(size_t)k * FDIM + tid];
        g_c[g][tid] = a;
    }
}

// ---------------- degree / norm / aggregation (measured ~100us) ---------------
__global__ void k_init_deg() {
    int i = blockIdx.x * blockDim.x + threadIdx.x;
    if (i < N_NODES) g_deg[i] = 1.0f;
}

__global__ void k_deg_acc(const int* __restrict__ ei,
                          const float* __restrict__ ew) {
    for (int e = blockIdx.x * blockDim.x + threadIdx.x; e < E_EDGES;
         e += gridDim.x * blockDim.x) {
        int d = ei[E_EDGES + e];
        atomicAdd(&g_deg[d], ew[e]);
    }
}

__global__ void k_dinv_self(const float* __restrict__ x) {
    int warp = (blockIdx.x * blockDim.x + threadIdx.x) >> 5;
    int lane = threadIdx.x & 31;
    if (warp >= N_NODES) return;
    float s;
    if (lane == 0) {
        float dg = g_deg[warp];
        s = (dg > 0.0f) ? rsqrtf(dg) : 0.0f;
        g_dinv[warp] = s;
    }
    s = __shfl_sync(0xffffffffu, s, 0);
    float s2 = s * s;
    size_t off = (size_t)warp * FDIM + lane * 4;
    float4 v = *(const float4*)(x + off);
    v.x *= s2; v.y *= s2; v.z *= s2; v.w *= s2;
    *(float4*)(g_agg + off) = v;
}

__global__ void k_edge_agg(const int* __restrict__ ei,
                           const float* __restrict__ ew,
                           const float* __restrict__ x) {
    int warp = (blockIdx.x * blockDim.x + threadIdx.x) >> 5;
    int lane = threadIdx.x & 31;
    if (warp >= E_EDGES) return;
    int s = 0, d = 0;
    float norm = 0.0f;
    if (lane == 0) {
        s = ei[warp];
        d = ei[E_EDGES + warp];
        norm = g_dinv[s] * ew[warp] * g_dinv[d];
    }
    s = __shfl_sync(0xffffffffu, s, 0);
    d = __shfl_sync(0xffffffffu, d, 0);
    norm = __shfl_sync(0xffffffffu, norm, 0);
    float4 v = *(const float4*)(x + (size_t)s * FDIM + lane * 4);
    float* p = g_agg + (size_t)d * FDIM + lane * 4;
    asm volatile("red.global.add.v4.f32 [%0], {%1,%2,%3,%4};"
                 :: "l"(p), "f"(v.x * norm), "f"(v.y * norm),
                    "f"(v.z * norm), "f"(v.w * norm)
                 : "memory");
}

// ============= tf32 tensor-core GEMM, cp.async double-buffered ================
__device__ __forceinline__ void cp16(void* s, const void* g, bool pred) {
    unsigned sa = (unsigned)__cvta_generic_to_shared(s);
    int sz = pred ? 16 : 0;
    asm volatile("cp.async.cg.shared.global [%0], [%1], 16, %2;\n"
                 :: "r"(sa), "l"(g), "r"(sz));
}
#define CP_COMMIT asm volatile("cp.async.commit_group;\n" ::: "memory")
#define CP_WAIT1  asm volatile("cp.async.wait_group 1;\n" ::: "memory")
#define CP_WAIT0  asm volatile("cp.async.wait_group 0;\n" ::: "memory")

__device__ __forceinline__ void mma8(float* c, unsigned a0, unsigned a1,
                                     unsigned a2, unsigned a3,
                                     unsigned b0, unsigned b1) {
    asm volatile("mma.sync.aligned.m16n8k8.row.col.f32.tf32.tf32.f32 "
        "{%0,%1,%2,%3},{%4,%5,%6,%7},{%8,%9},{%0,%1,%2,%3};"
        : "+f"(c[0]), "+f"(c[1]), "+f"(c[2]), "+f"(c[3])
        : "r"(a0), "r"(a1), "r"(a2), "r"(a3), "r"(b0), "r"(b1));
}

// Block 128x128, 256 thr = 8 warps (2 row x 4 col), warp tile 64x32.
// K-chunk = 16, ping-pong. As stride 20, Ws stride 136: both conflict-free.
#define TC_DECL                                                            \
    __shared__ float As[2][128][20];                                       \
    __shared__ float Ws[2][16][136];                                       \
    int tid = threadIdx.x;                                                 \
    int lane = tid & 31, wid = tid >> 5;                                   \
    int qid = lane >> 2, qtid = lane & 3;                                  \
    int wr = (wid >> 2) * 64, wc = (wid & 3) * 32;                         \
    int row0 = blockIdx.x * 128;                                           \
    float acc[4][4][4] = {};

#define TC_LOAD_A(buf, Asrc, colbase)                                      \
    _Pragma("unroll")                                                      \
    for (int t = 0; t < 2; t++) {                                          \
        int idx = tid + t * 256;                                           \
        int r = idx >> 2, c = (idx & 3) * 4;                               \
        cp16(&As[buf][r][c],                                               \
             (Asrc) + (size_t)(row0 + r) * FDIM + (colbase) + c,           \
             (row0 + r) < N_NODES);                                        \
    }

#define TC_LOAD_W(buf, Wsrc, kb)                                           \
    _Pragma("unroll")                                                      \
    for (int t = 0; t < 2; t++) {                                          \
        int idx = tid + t * 256;                                           \
        int r = idx >> 5, c = (idx & 31) * 4;                              \
        cp16(&Ws[buf][r][c], (Wsrc) + (size_t)((kb) + r) * FDIM + c, true);\
    }

#define TC_COMPUTE(b)                                                      \
    _Pragma("unroll")                                                      \
    for (int ks = 0; ks < 16; ks += 8) {                                   \
        unsigned af[4][4], bf[4][2];                                       \
        _Pragma("unroll")                                                  \
        for (int m = 0; m < 4; m++) {                                      \
            int r = wr + 16 * m + qid;                                     \
            af[m][0] = __float_as_uint(As[b][r][ks + qtid]);               \
            af[m][1] = __float_as_uint(As[b][r + 8][ks + qtid]);           \
            af[m][2] = __float_as_uint(As[b][r][ks + qtid + 4]);           \
            af[m][3] = __float_as_uint(As[b][r + 8][ks + qtid + 4]);       \
        }                                                                  \
        _Pragma("unroll")                                                  \
        for (int n = 0; n < 4; n++) {                                      \
            int cc = wc + 8 * n + qid;                                     \
            bf[n][0] = __float_as_uint(Ws[b][ks + qtid][cc]);              \
            bf[n][1] = __float_as_uint(Ws[b][ks + qtid + 4][cc]);          \
        }                                                                  \
        _Pragma("unroll")                                                  \
        for (int m = 0; m < 4; m++)                                        \
            _Pragma("unroll")                                              \
            for (int n = 0; n < 4; n++)                                    \
                mma8(acc[m][n], af[m][0], af[m][1], af[m][2], af[m][3],    \
                     bf[n][0], bf[n][1]);                                  \
    }

// ------- GEMM A: Z = sig(...); R path stores H*R directly --------------------
__global__ void __launch_bounds__(256, 2)
k_zr_gemm(const float* __restrict__ H) {
    int which = blockIdx.y;          // 0=Z, 1=R(->H*R)
    const float* Wc = g_Wcomb[which];
    const float* cb = g_c[which];
    float* C = (which == 0) ? g_Z : g_R;

    TC_DECL
    TC_LOAD_A(0, g_agg, 0)
    TC_LOAD_W(0, Wc, 0)
    CP_COMMIT;
    for (int kk = 0; kk < 16; kk++) {
        if (kk + 1 < 16) {
            int nk = kk + 1;
            const float* Asrc = (nk < 8) ? g_agg : H;
            TC_LOAD_A(nk & 1, Asrc, (nk & 7) * 16)
            TC_LOAD_W(nk & 1, Wc, nk * 16)
            CP_COMMIT; CP_WAIT1;
        } else { CP_WAIT0; }
        __syncthreads();
        TC_COMPUTE(kk & 1)
        __syncthreads();
    }
    #pragma unroll
    for (int m = 0; m < 4; m++) {
        #pragma unroll
        for (int n = 0; n < 4; n++) {
            int col = wc + 8 * n + 2 * qtid;
            float b0v = cb[col], b1v = cb[col + 1];
            #pragma unroll
            for (int h = 0; h < 2; h++) {
                int row = row0 + wr + 16 * m + qid + 8 * h;
                if (row < N_NODES) {
                    float2 o;
                    o.x = 1.0f / (1.0f + __expf(-(acc[m][n][2 * h] + b0v)));
                    o.y = 1.0f / (1.0f + __expf(-(acc[m][n][2 * h + 1] + b1v)));
                    if (which == 1) {   // fuse H*R
                        float2 hv = *(const float2*)(H + (size_t)row * FDIM + col);
                        o.x *= hv.x; o.y *= hv.y;
                    }
                    *(float2*)(C + (size_t)row * FDIM + col) = o;
                }
            }
        }
    }
}

// ------ GEMM B: Ht = tanh(agg@Mh + (H*R)@Ph + ch); h = Z*H+(1-Z)*Ht ----------
__global__ void __launch_bounds__(256, 2)
k_final(const float* __restrict__ H, float* __restrict__ h_out) {
    const float* Wc = g_Wcomb[2];
    const float* cb = g_c[2];

    TC_DECL
    TC_LOAD_A(0, g_agg, 0)
    TC_LOAD_W(0, Wc, 0)
    CP_COMMIT;
    for (int kk = 0; kk < 16; kk++) {
        if (kk + 1 < 16) {
            int nk = kk + 1;
            const float* Asrc = (nk < 8) ? g_agg : g_R;   // g_R holds H*R
            TC_LOAD_A(nk & 1, Asrc, (nk & 7) * 16)
            TC_LOAD_W(nk & 1, Wc, nk * 16)
            CP_COMMIT; CP_WAIT1;
        } else { CP_WAIT0; }
        __syncthreads();
        TC_COMPUTE(kk & 1)
        __syncthreads();
    }
    #pragma unroll
    for (int m = 0; m < 4; m++) {
        #pragma unroll
        for (int n = 0; n < 4; n++) {
            int col = wc + 8 * n + 2 * qtid;
            float b0v = cb[col], b1v = cb[col + 1];
            #pragma unroll
            for (int h = 0; h < 2; h++) {
                int row = row0 + wr + 16 * m + qid + 8 * h;
                if (row < N_NODES) {
                    float2 zv = *(const float2*)(g_Z + (size_t)row * FDIM + col);
                    float2 hv = *(const float2*)(H + (size_t)row * FDIM + col);
                    float x0 = acc[m][n][2 * h] + b0v;
                    float x1 = acc[m][n][2 * h + 1] + b1v;
                    float t0 = 1.0f - 2.0f / (__expf(2.0f * x0) + 1.0f);
                    float t1 = 1.0f - 2.0f / (__expf(2.0f * x1) + 1.0f);
                    float2 hr;
                    hr.x = zv.x * hv.x + (1.0f - zv.x) * t0;
                    hr.y = zv.y * hv.y + (1.0f - zv.y) * t1;
                    *(float2*)(h_out + (size_t)row * FDIM + col) = hr;
                    float2 rl = make_float2(fmaxf(hr.x, 0.0f), fmaxf(hr.y, 0.0f));
                    *(float2*)(g_relu + (size_t)row * FDIM + col) = rl;
                }
            }
        }
    }
}

// ---------------- readout: y = relu(h) @ Wo + bo ------------------------------
__global__ void __launch_bounds__(128)
k_readout(const float* __restrict__ Wo, const float* __restrict__ bo,
          float* __restrict__ y_out) {
    __shared__ float Wos[FDIM * OUTD + OUTD];
    int tid = threadIdx.x;
    for (int t = tid; t < FDIM * OUTD; t += 128) Wos[t] = Wo[t];
    if (tid < OUTD) Wos[FDIM * OUTD + tid] = bo[tid];
    __syncthreads();
    int row = blockIdx.x * 128 + tid;
    if (row >= N_NODES) return;
    const float* hr = g_relu + (size_t)row * FDIM;
    float acc[OUTD] = {};
    #pragma unroll 4
    for (int k4 = 0; k4 < FDIM / 4; k4++) {
        float4 hv = *(const float4*)(hr + k4 * 4);
        float hvv[4] = {hv.x, hv.y, hv.z, hv.w};
        #pragma unroll
        for (int j = 0; j < 4; j++)
            #pragma unroll
            for (int o = 0; o < OUTD; o++)
                acc[o] += hvv[j] * Wos[(k4 * 4 + j) * OUTD + o];
    }
    #pragma unroll
    for (int o = 0; o < OUTD; o++)
        y_out[(size_t)row * OUTD + o] = acc[o] + Wos[FDIM * OUTD + o];
}

// ---------------- launch ------------------------------------------------------
extern "C" void kernel_launch(void* const* d_in, const int* in_sizes, int n_in,
                              void* d_out, int out_size) {
    const float* x  = (const float*)d_in[0];
    const int*   ei = (const int*)d_in[1];
    const float* ew = (const float*)d_in[2];
    const float* H  = (const float*)d_in[3];
    const float* Wz = (const float*)d_in[4];
    const float* bz = (const float*)d_in[5];
    const float* Wr = (const float*)d_in[6];
    const float* br = (const float*)d_in[7];
    const float* Wh = (const float*)d_in[8];
    const float* bh = (const float*)d_in[9];
    const float* Lz = (const float*)d_in[10];
    const float* lbz = (const float*)d_in[11];
    const float* Lr = (const float*)d_in[12];
    const float* lbr = (const float*)d_in[13];
    const float* Lh = (const float*)d_in[14];
    const float* lbh = (const float*)d_in[15];
    const float* Wo = (const float*)d_in[16];
    const float* bo = (const float*)d_in[17];

    float* y_out = (float*)d_out;                           // (N, 12)
    float* h_out = (float*)d_out + (size_t)N_NODES * OUTD;  // (N, 128)

    int nblk = (N_NODES + 127) / 128;   // 391

    k_prep_m<<<dim3(2, 3), 256>>>(Wz, Wr, Wh, Lz, Lr, Lh);
    k_prep_rest<<<3, 256>>>(Lz, Lr, Lh, bz, br, bh, lbz, lbr, lbh);
    k_init_deg<<<(N_NODES + 255) / 256, 256>>>();
    k_deg_acc<<<592, 256>>>(ei, ew);
    k_dinv_self<<<(N_NODES * 32 + 255) / 256, 256>>>(x);
    k_edge_agg<<<(E_EDGES * 32 + 255) / 256, 256>>>(ei, ew, x);
    k_zr_gemm<<<dim3(nblk, 2), 256>>>(H);
    k_final<<<nblk, 256>>>(H, h_out);
    k_readout<<<nblk, 128>>>(Wo, bo, y_out);
}